// round 14
// baseline (speedup 1.0000x reference)
#include <cuda_runtime.h>
#include <math.h>

#define CB 8
#define CT 1024
#define CE 1024
#define CH 16
#define CD 64

// Scratch (device globals). Layout [b*H+h][t][64] contiguous.
__device__ float g_V  [CB*CH*CT*CD];
__device__ float g_NW [CB*CH*CT*CD];

// ---------------------------------------------------------------------------
// helpers
// ---------------------------------------------------------------------------
__device__ __forceinline__ unsigned f2tf32(float x) {
    unsigned r;
    asm("cvt.rna.tf32.f32 %0, %1;" : "=r"(r) : "f"(x));
    return r;
}
__device__ __forceinline__ float rnd_tf32(float x) {
    return __uint_as_float(f2tf32(x));
}
__device__ __forceinline__ float ex2_fast(float x) {
    float y;
    asm("ex2.approx.f32 %0, %1;" : "=f"(y) : "f"(x));
    return y;
}
__device__ __forceinline__ float tanh_fast(float x) {
    float y;
    asm("tanh.approx.f32 %0, %1;" : "=f"(y) : "f"(x));
    return y;
}
__device__ __forceinline__ void mma_tf32(float* d,
    unsigned a0, unsigned a1, unsigned a2, unsigned a3,
    unsigned b0, unsigned b1)
{
    asm volatile(
        "mma.sync.aligned.m16n8k8.row.col.f32.tf32.tf32.f32 "
        "{%0,%1,%2,%3}, {%4,%5,%6,%7}, {%8,%9}, {%0,%1,%2,%3};"
        : "+f"(d[0]), "+f"(d[1]), "+f"(d[2]), "+f"(d[3])
        : "r"(a0), "r"(a1), "r"(a2), "r"(a3), "r"(b0), "r"(b1));
}
__device__ __forceinline__ void cp_async16(unsigned saddr, const void* gptr) {
    asm volatile("cp.async.cg.shared.global [%0], [%1], 16;"
                 :: "r"(saddr), "l"(gptr));
}
#define CP_COMMIT() asm volatile("cp.async.commit_group;")
#define CP_WAIT0()  asm volatile("cp.async.wait_group 0;")

// ---------------------------------------------------------------------------
// Fused pre-kernel: blocks 0..127 run the RNN chains (latency-bound),
// blocks 128..1151 run the V head-projection (DRAM/tensor-bound) — concurrent.
// ---------------------------------------------------------------------------
__global__ __launch_bounds__(128) void fused_pre_kernel(
    const float* __restrict__ target,
    const float* __restrict__ W_v,
    const float* __restrict__ W_ih, const float* __restrict__ W_hh,
    const float* __restrict__ b_ih, const float* __restrict__ b_hh,
    float* __restrict__ NW, float* __restrict__ Vout)
{
    const int tid = threadIdx.x;

    if (blockIdx.x < 128) {
        // ================= RNN path =================
        const int bh = blockIdx.x;
        const int b = bh >> 4, h = bh & 15;
        const int e = tid >> 1, half = tid & 1;
        __shared__ float hs[2][64];

        float w[32];
        const float* wih = W_ih + h * 4096 + e * 64 + half * 32;
#pragma unroll
        for (int j = 0; j < 32; j++) w[j] = wih[j];
        const float bsum = b_ih[h * 64 + e] + b_hh[h * 64 + e];

        if (half == 0)
            hs[0][e] = target[(size_t)b * CT * CE + h * 64 + e];
        __syncthreads();

        // step 1: W_ih only
        {
            float a0 = 0.f, a1 = 0.f, a2 = 0.f, a3 = 0.f;
            const float* hb = &hs[0][half * 32];
#pragma unroll
            for (int j = 0; j < 8; j++) {
                float4 hv = *(const float4*)&hb[j * 4];
                a0 += hv.x * w[j * 4 + 0];
                a1 += hv.y * w[j * 4 + 1];
                a2 += hv.z * w[j * 4 + 2];
                a3 += hv.w * w[j * 4 + 3];
            }
            float part = (a0 + a1) + (a2 + a3);
            part += __shfl_xor_sync(0xffffffffu, part, 1);
            float hcur = tanh_fast(part + bsum);
            if (half == 0) {
                NW[(size_t)bh * CT * 64 + e] = rnd_tf32(hcur);
                hs[1][e] = hcur;
            }
        }
        const float* whh = W_hh + h * 4096 + e * 64 + half * 32;
#pragma unroll
        for (int j = 0; j < 32; j++) w[j] += whh[j];
        __syncthreads();

        float* nwp = NW + (size_t)bh * CT * 64 + e;
        int p = 1;
        for (int t = 1; t < CT; t++) {
            float a0 = 0.f, a1 = 0.f, a2 = 0.f, a3 = 0.f;
            const float* hb = &hs[p][half * 32];
#pragma unroll
            for (int j = 0; j < 8; j++) {
                float4 hv = *(const float4*)&hb[j * 4];
                a0 += hv.x * w[j * 4 + 0];
                a1 += hv.y * w[j * 4 + 1];
                a2 += hv.z * w[j * 4 + 2];
                a3 += hv.w * w[j * 4 + 3];
            }
            float part = (a0 + a1) + (a2 + a3);
            part += __shfl_xor_sync(0xffffffffu, part, 1);
            float hn = tanh_fast(part + bsum);
            if (half == 0) {
                nwp[(size_t)t * 64] = rnd_tf32(hn);
                hs[p ^ 1][e] = hn;
            }
            __syncthreads();
            p ^= 1;
        }
    } else {
        // ================= V projection path (tf32 mma) =================
        extern __shared__ unsigned psm[];
        float*    Xs = (float*)psm;            // 128 x 68 raw floats
        unsigned* Ws = psm + 128 * 68;         // 64 x 68 tf32 bits

        const int idx = blockIdx.x - 128;
        const int tile = idx & 7;              // CT/128 = 8 tiles
        const int bh = idx >> 3;
        const int b = bh >> 4, h = bh & 15;
        const int t0 = tile << 7;
        const float* Xp = target + (size_t)b * CT * CE + h * 64 + (size_t)t0 * CE;
        float* Yp = Vout + (size_t)bh * CT * 64 + (size_t)t0 * 64;
        const float* Wp = W_v + h * 4096;
        const int wid = tid >> 5, lane = tid & 31;
        const int g = lane >> 2, c = lane & 3;
        const int m0 = wid * 32;

#pragma unroll
        for (int k = 0; k < 16; k++) {
            int i = tid + k * 128;
            int r = i >> 4, c4 = i & 15;
            float4 v = *(const float4*)(Xp + (size_t)r * CE + c4 * 4);
            *(float4*)&Xs[r * 68 + c4 * 4] = v;
        }
#pragma unroll
        for (int k = 0; k < 8; k++) {
            int i = tid + k * 128;
            int d = i >> 4, c4 = i & 15;
            float4 v = *(const float4*)(Wp + d * 64 + c4 * 4);
            uint4 u = make_uint4(f2tf32(v.x), f2tf32(v.y), f2tf32(v.z), f2tf32(v.w));
            *(uint4*)&Ws[d * 68 + c4 * 4] = u;
        }
        __syncthreads();

        float acc0[8][4], acc1[8][4];
#pragma unroll
        for (int nb = 0; nb < 8; nb++)
#pragma unroll
            for (int k = 0; k < 4; k++) { acc0[nb][k] = 0.f; acc1[nb][k] = 0.f; }

#pragma unroll
        for (int kc = 0; kc < 8; kc++) {
            unsigned a0 = f2tf32(Xs[(m0 + g)      * 68 + kc * 8 + c]);
            unsigned a1 = f2tf32(Xs[(m0 + g + 8)  * 68 + kc * 8 + c]);
            unsigned a2 = f2tf32(Xs[(m0 + g)      * 68 + kc * 8 + c + 4]);
            unsigned a3 = f2tf32(Xs[(m0 + g + 8)  * 68 + kc * 8 + c + 4]);
            unsigned e0 = f2tf32(Xs[(m0 + g + 16) * 68 + kc * 8 + c]);
            unsigned e1 = f2tf32(Xs[(m0 + g + 24) * 68 + kc * 8 + c]);
            unsigned e2 = f2tf32(Xs[(m0 + g + 16) * 68 + kc * 8 + c + 4]);
            unsigned e3 = f2tf32(Xs[(m0 + g + 24) * 68 + kc * 8 + c + 4]);
#pragma unroll
            for (int nb = 0; nb < 8; nb++) {
                unsigned b0 = Ws[(kc * 8 + c)     * 68 + nb * 8 + g];
                unsigned b1 = Ws[(kc * 8 + c + 4) * 68 + nb * 8 + g];
                mma_tf32(acc0[nb], a0, a1, a2, a3, b0, b1);
                mma_tf32(acc1[nb], e0, e1, e2, e3, b0, b1);
            }
        }
        // V rounded to tf32 at production so attention eats raw bits
#pragma unroll
        for (int nb = 0; nb < 8; nb++) {
            *(float2*)(Yp + (size_t)(m0 + g)      * 64 + nb * 8 + 2 * c) = make_float2(rnd_tf32(acc0[nb][0]), rnd_tf32(acc0[nb][1]));
            *(float2*)(Yp + (size_t)(m0 + g + 8)  * 64 + nb * 8 + 2 * c) = make_float2(rnd_tf32(acc0[nb][2]), rnd_tf32(acc0[nb][3]));
            *(float2*)(Yp + (size_t)(m0 + g + 16) * 64 + nb * 8 + 2 * c) = make_float2(rnd_tf32(acc1[nb][0]), rnd_tf32(acc1[nb][1]));
            *(float2*)(Yp + (size_t)(m0 + g + 24) * 64 + nb * 8 + 2 * c) = make_float2(rnd_tf32(acc1[nb][2]), rnd_tf32(acc1[nb][3]));
        }
    }
}

// ---------------------------------------------------------------------------
// Fused attention: Q-projection prologue + flash attention mainloop (tf32 mma,
// cp.async double-buffered K/V, max-free softmax, shfl P-transpose) +
// O-projection epilogue writing d_out directly.
// Smem: [K0][V0][K1][V1] (4 x 64x68) + [Wbuf 64x68] + [Qpk 4096].
// ---------------------------------------------------------------------------
#define AST 68
#define TILE_W (64 * AST)                      // 4352 words
#define SM_WBUF (4 * TILE_W)                   // 17408
#define SM_QPK (SM_WBUF + TILE_W)              // 21760
#define SM_ATTN_WORDS (SM_QPK + 4096)          // 25856 words = 103424 B

__global__ __launch_bounds__(128, 2) void attn_fused_kernel(
    const float* __restrict__ source, const float* __restrict__ W_q,
    const float* __restrict__ K, const float* __restrict__ V,
    const float* __restrict__ W_o, float* __restrict__ out)
{
    extern __shared__ unsigned sm[];
    unsigned* Wbuf = sm + SM_WBUF;
    unsigned* Qpk  = sm + SM_QPK;
    const unsigned sbase = (unsigned)__cvta_generic_to_shared(sm);

    const int bh = blockIdx.y;
    const int b = bh >> 4, h = bh & 15;
    const int q0 = blockIdx.x << 7;
    const int tid = threadIdx.x;
    const int wid = tid >> 5, lane = tid & 31;
    const int g = lane >> 2, c = lane & 3;
    const int m0 = wid * 32;

    const float* Kp = K + (size_t)bh * CT * 64;
    const float* Vp = V + (size_t)bh * CT * 64;

    // ---- kick off K/V tile 0 into buffer 0 ----
#pragma unroll
    for (int k = 0; k < 8; k++) {
        int i = tid + k * 128;
        int r = i >> 4, c4 = i & 15;
        unsigned off = (unsigned)(r * AST + c4 * 4) * 4u;
        cp_async16(sbase + off, Kp + r * 64 + c4 * 4);
        cp_async16(sbase + TILE_W * 4u + off, Vp + r * 64 + c4 * 4);
    }
    CP_COMMIT();

    // ---- Q-projection prologue (overlaps tile-0 DMA) ----
    // stage X tile (source[b, q0.., h*64..]) into K1/V1 area; Wq*qscale into Wbuf
    {
        float* Qstage = (float*)(sm + 2 * TILE_W);   // 128 x 68
        const float* Xp = source + (size_t)b * CT * CE + h * 64 + (size_t)q0 * CE;
#pragma unroll
        for (int k = 0; k < 16; k++) {
            int i = tid + k * 128;
            int r = i >> 4, c4 = i & 15;
            float4 v = *(const float4*)(Xp + (size_t)r * CE + c4 * 4);
            *(float4*)&Qstage[r * AST + c4 * 4] = v;
        }
        const float qscale = 1.4426950408889634f / 256.0f;  // log2(e)/(8*32)
        const float* Wp = W_q + h * 4096;
#pragma unroll
        for (int k = 0; k < 8; k++) {
            int i = tid + k * 128;
            int d = i >> 4, c4 = i & 15;
            float4 v = *(const float4*)(Wp + d * 64 + c4 * 4);
            uint4 u = make_uint4(f2tf32(v.x * qscale), f2tf32(v.y * qscale),
                                 f2tf32(v.z * qscale), f2tf32(v.w * qscale));
            *(uint4*)&Wbuf[d * 68 + c4 * 4] = u;
        }
    }
    __syncthreads();

    // Q = X @ (Wq*qscale), C-frag accumulate
    float qc0[8][4], qc1[8][4];
#pragma unroll
    for (int nb = 0; nb < 8; nb++)
#pragma unroll
        for (int k = 0; k < 4; k++) { qc0[nb][k] = 0.f; qc1[nb][k] = 0.f; }
    {
        const float* Qstage = (const float*)(sm + 2 * TILE_W);
#pragma unroll
        for (int kc = 0; kc < 8; kc++) {
            unsigned a0 = f2tf32(Qstage[(m0 + g)      * AST + kc * 8 + c]);
            unsigned a1 = f2tf32(Qstage[(m0 + g + 8)  * AST + kc * 8 + c]);
            unsigned a2 = f2tf32(Qstage[(m0 + g)      * AST + kc * 8 + c + 4]);
            unsigned a3 = f2tf32(Qstage[(m0 + g + 8)  * AST + kc * 8 + c + 4]);
            unsigned e0 = f2tf32(Qstage[(m0 + g + 16) * AST + kc * 8 + c]);
            unsigned e1 = f2tf32(Qstage[(m0 + g + 24) * AST + kc * 8 + c]);
            unsigned e2 = f2tf32(Qstage[(m0 + g + 16) * AST + kc * 8 + c + 4]);
            unsigned e3 = f2tf32(Qstage[(m0 + g + 24) * AST + kc * 8 + c + 4]);
#pragma unroll
            for (int nb = 0; nb < 8; nb++) {
                unsigned b0 = Wbuf[(kc * 8 + c)     * 68 + nb * 8 + g];
                unsigned b1 = Wbuf[(kc * 8 + c + 4) * 68 + nb * 8 + g];
                mma_tf32(qc0[nb], a0, a1, a2, a3, b0, b1);
                mma_tf32(qc1[nb], e0, e1, e2, e3, b0, b1);
            }
        }
    }
    // transpose Q C-frags -> A-frags (half0 regs, half1 -> Qpk)
    unsigned qa[8][4];
#pragma unroll
    for (int kc = 0; kc < 8; kc++) {
        const int srcA = (lane & ~3) | (c >> 1);
        const int srcB = srcA + 2;
        float t0, t1;
        t0 = __shfl_sync(0xffffffffu, qc0[kc][0], srcA);
        t1 = __shfl_sync(0xffffffffu, qc0[kc][1], srcA);
        qa[kc][0] = f2tf32((c & 1) ? t1 : t0);
        t0 = __shfl_sync(0xffffffffu, qc0[kc][2], srcA);
        t1 = __shfl_sync(0xffffffffu, qc0[kc][3], srcA);
        qa[kc][1] = f2tf32((c & 1) ? t1 : t0);
        t0 = __shfl_sync(0xffffffffu, qc0[kc][0], srcB);
        t1 = __shfl_sync(0xffffffffu, qc0[kc][1], srcB);
        qa[kc][2] = f2tf32((c & 1) ? t1 : t0);
        t0 = __shfl_sync(0xffffffffu, qc0[kc][2], srcB);
        t1 = __shfl_sync(0xffffffffu, qc0[kc][3], srcB);
        qa[kc][3] = f2tf32((c & 1) ? t1 : t0);

        uint4 qb;
        t0 = __shfl_sync(0xffffffffu, qc1[kc][0], srcA);
        t1 = __shfl_sync(0xffffffffu, qc1[kc][1], srcA);
        qb.x = f2tf32((c & 1) ? t1 : t0);
        t0 = __shfl_sync(0xffffffffu, qc1[kc][2], srcA);
        t1 = __shfl_sync(0xffffffffu, qc1[kc][3], srcA);
        qb.y = f2tf32((c & 1) ? t1 : t0);
        t0 = __shfl_sync(0xffffffffu, qc1[kc][0], srcB);
        t1 = __shfl_sync(0xffffffffu, qc1[kc][1], srcB);
        qb.z = f2tf32((c & 1) ? t1 : t0);
        t0 = __shfl_sync(0xffffffffu, qc1[kc][2], srcB);
        t1 = __shfl_sync(0xffffffffu, qc1[kc][3], srcB);
        qb.w = f2tf32((c & 1) ? t1 : t0);
        *(uint4*)&Qpk[((wid * 8 + kc) * 32 + lane) * 4] = qb;
    }

    // ---- mainloop ----
    float oacc0[8][4], oacc1[8][4];
#pragma unroll
    for (int nb = 0; nb < 8; nb++)
#pragma unroll
        for (int k = 0; k < 4; k++) { oacc0[nb][k] = 0.f; oacc1[nb][k] = 0.f; }
    float lacc00 = 0.f, lacc01 = 0.f, lacc10 = 0.f, lacc11 = 0.f;

    for (int kt = 0; kt < 16; kt++) {
        CP_WAIT0();
        __syncthreads();

        if (kt < 15) {
            const float* Kt = Kp + (kt + 1) * 64 * 64;
            const float* Vt = Vp + (kt + 1) * 64 * 64;
            unsigned bofs = ((kt + 1) & 1) ? 2u * TILE_W * 4u : 0u;
#pragma unroll
            for (int k = 0; k < 8; k++) {
                int i = tid + k * 128;
                int r = i >> 4, c4 = i & 15;
                unsigned off = (unsigned)(r * AST + c4 * 4) * 4u;
                cp_async16(sbase + bofs + off, Kt + r * 64 + c4 * 4);
                cp_async16(sbase + bofs + TILE_W * 4u + off, Vt + r * 64 + c4 * 4);
            }
            CP_COMMIT();
        }

        const unsigned* Kr = sm + ((kt & 1) ? 2 * TILE_W : 0);
        const unsigned* Vr = Kr + TILE_W;

        // S = Q @ K^T (raw pre-rounded tf32 bits from smem)
        float s0[8][4], s1[8][4];
#pragma unroll
        for (int nb = 0; nb < 8; nb++)
#pragma unroll
            for (int k = 0; k < 4; k++) { s0[nb][k] = 0.f; s1[nb][k] = 0.f; }
#pragma unroll
        for (int kc = 0; kc < 8; kc++) {
            uint4 qb = *(const uint4*)&Qpk[((wid * 8 + kc) * 32 + lane) * 4];
#pragma unroll
            for (int nb = 0; nb < 8; nb++) {
                unsigned b0 = Kr[(nb * 8 + g) * AST + kc * 8 + c];
                unsigned b1 = Kr[(nb * 8 + g) * AST + kc * 8 + c + 4];
                mma_tf32(s0[nb], qa[kc][0], qa[kc][1], qa[kc][2], qa[kc][3], b0, b1);
                mma_tf32(s1[nb], qb.x, qb.y, qb.z, qb.w, b0, b1);
            }
        }

        // max-free softmax: P = 2^s
#pragma unroll
        for (int nb = 0; nb < 8; nb++) {
            s0[nb][0] = ex2_fast(s0[nb][0]); lacc00 += s0[nb][0];
            s0[nb][1] = ex2_fast(s0[nb][1]); lacc00 += s0[nb][1];
            s0[nb][2] = ex2_fast(s0[nb][2]); lacc01 += s0[nb][2];
            s0[nb][3] = ex2_fast(s0[nb][3]); lacc01 += s0[nb][3];
            s1[nb][0] = ex2_fast(s1[nb][0]); lacc10 += s1[nb][0];
            s1[nb][1] = ex2_fast(s1[nb][1]); lacc10 += s1[nb][1];
            s1[nb][2] = ex2_fast(s1[nb][2]); lacc11 += s1[nb][2];
            s1[nb][3] = ex2_fast(s1[nb][3]); lacc11 += s1[nb][3];
        }

        // O += P @ V (P transposed C-frag -> A-frag via shfl)
#pragma unroll
        for (int jc = 0; jc < 8; jc++) {
            const int srcA = (lane & ~3) | (c >> 1);
            const int srcB = srcA + 2;
            float t0, t1;
            unsigned pa0, pa1, pa2, pa3, pb0, pb1, pb2, pb3;
            t0 = __shfl_sync(0xffffffffu, s0[jc][0], srcA);
            t1 = __shfl_sync(0xffffffffu, s0[jc][1], srcA);
            pa0 = f2tf32((c & 1) ? t1 : t0);
            t0 = __shfl_sync(0xffffffffu, s0[jc][2], srcA);
            t1 = __shfl_sync(0xffffffffu, s0[jc][3], srcA);
            pa1 = f2tf32((c & 1) ? t1 : t0);
            t0 = __shfl_sync(0xffffffffu, s0[jc][0], srcB);
            t1 = __shfl_sync(0xffffffffu, s0[jc][1], srcB);
            pa2 = f2tf32((c & 1) ? t1 : t0);
            t0 = __shfl_sync(0xffffffffu, s0[jc][2], srcB);
            t1 = __shfl_sync(0xffffffffu, s0[jc][3], srcB);
            pa3 = f2tf32((c & 1) ? t1 : t0);

            t0 = __shfl_sync(0xffffffffu, s1[jc][0], srcA);
            t1 = __shfl_sync(0xffffffffu, s1[jc][1], srcA);
            pb0 = f2tf32((c & 1) ? t1 : t0);
            t0 = __shfl_sync(0xffffffffu, s1[jc][2], srcA);
            t1 = __shfl_sync(0xffffffffu, s1[jc][3], srcA);
            pb1 = f2tf32((c & 1) ? t1 : t0);
            t0 = __shfl_sync(0xffffffffu, s1[jc][0], srcB);
            t1 = __shfl_sync(0xffffffffu, s1[jc][1], srcB);
            pb2 = f2tf32((c & 1) ? t1 : t0);
            t0 = __shfl_sync(0xffffffffu, s1[jc][2], srcB);
            t1 = __shfl_sync(0xffffffffu, s1[jc][3], srcB);
            pb3 = f2tf32((c & 1) ? t1 : t0);

#pragma unroll
            for (int nb = 0; nb < 8; nb++) {
                unsigned vb0 = Vr[(jc * 8 + c)     * AST + nb * 8 + g];
                unsigned vb1 = Vr[(jc * 8 + c + 4) * AST + nb * 8 + g];
                mma_tf32(oacc0[nb], pa0, pa1, pa2, pa3, vb0, vb1);
                mma_tf32(oacc1[nb], pb0, pb1, pb2, pb3, vb0, vb1);
            }
        }
    }

    // ---- normalize ----
    float l00 = lacc00, l01 = lacc01, l10 = lacc10, l11 = lacc11;
#pragma unroll
    for (int off = 1; off <= 2; off <<= 1) {
        l00 += __shfl_xor_sync(0xffffffffu, l00, off);
        l01 += __shfl_xor_sync(0xffffffffu, l01, off);
        l10 += __shfl_xor_sync(0xffffffffu, l10, off);
        l11 += __shfl_xor_sync(0xffffffffu, l11, off);
    }
    float i00 = 1.f / l00, i01 = 1.f / l01, i10 = 1.f / l10, i11 = 1.f / l11;
#pragma unroll
    for (int nb = 0; nb < 8; nb++) {
        oacc0[nb][0] *= i00; oacc0[nb][1] *= i00;
        oacc0[nb][2] *= i01; oacc0[nb][3] *= i01;
        oacc1[nb][0] *= i10; oacc1[nb][1] *= i10;
        oacc1[nb][2] *= i11; oacc1[nb][3] *= i11;
    }

    // ---- O-projection epilogue: stage Wo into freed K0 buffer ----
    __syncthreads();     // all warps done with K/V buffers
    {
        const float* Wp = W_o + h * 4096;
#pragma unroll
        for (int k = 0; k < 8; k++) {
            int i = tid + k * 128;
            int d = i >> 4, c4 = i & 15;
            float4 v = *(const float4*)(Wp + d * 64 + c4 * 4);
            uint4 u = make_uint4(f2tf32(v.x), f2tf32(v.y), f2tf32(v.z), f2tf32(v.w));
            *(uint4*)&sm[d * 68 + c4 * 4] = u;
        }
    }
    __syncthreads();

    float f0[8][4], f1[8][4];
#pragma unroll
    for (int nb = 0; nb < 8; nb++)
#pragma unroll
        for (int k = 0; k < 4; k++) { f0[nb][k] = 0.f; f1[nb][k] = 0.f; }

#pragma unroll
    for (int kc = 0; kc < 8; kc++) {
        const int srcA = (lane & ~3) | (c >> 1);
        const int srcB = srcA + 2;
        float t0, t1;
        unsigned oa0, oa1, oa2, oa3, ob0, ob1, ob2, ob3;
        t0 = __shfl_sync(0xffffffffu, oacc0[kc][0], srcA);
        t1 = __shfl_sync(0xffffffffu, oacc0[kc][1], srcA);
        oa0 = f2tf32((c & 1) ? t1 : t0);
        t0 = __shfl_sync(0xffffffffu, oacc0[kc][2], srcA);
        t1 = __shfl_sync(0xffffffffu, oacc0[kc][3], srcA);
        oa1 = f2tf32((c & 1) ? t1 : t0);
        t0 = __shfl_sync(0xffffffffu, oacc0[kc][0], srcB);
        t1 = __shfl_sync(0xffffffffu, oacc0[kc][1], srcB);
        oa2 = f2tf32((c & 1) ? t1 : t0);
        t0 = __shfl_sync(0xffffffffu, oacc0[kc][2], srcB);
        t1 = __shfl_sync(0xffffffffu, oacc0[kc][3], srcB);
        oa3 = f2tf32((c & 1) ? t1 : t0);

        t0 = __shfl_sync(0xffffffffu, oacc1[kc][0], srcA);
        t1 = __shfl_sync(0xffffffffu, oacc1[kc][1], srcA);
        ob0 = f2tf32((c & 1) ? t1 : t0);
        t0 = __shfl_sync(0xffffffffu, oacc1[kc][2], srcA);
        t1 = __shfl_sync(0xffffffffu, oacc1[kc][3], srcA);
        ob1 = f2tf32((c & 1) ? t1 : t0);
        t0 = __shfl_sync(0xffffffffu, oacc1[kc][0], srcB);
        t1 = __shfl_sync(0xffffffffu, oacc1[kc][1], srcB);
        ob2 = f2tf32((c & 1) ? t1 : t0);
        t0 = __shfl_sync(0xffffffffu, oacc1[kc][2], srcB);
        t1 = __shfl_sync(0xffffffffu, oacc1[kc][3], srcB);
        ob3 = f2tf32((c & 1) ? t1 : t0);

#pragma unroll
        for (int nb = 0; nb < 8; nb++) {
            unsigned b0 = sm[(kc * 8 + c)     * 68 + nb * 8 + g];
            unsigned b1 = sm[(kc * 8 + c + 4) * 68 + nb * 8 + g];
            mma_tf32(f0[nb], oa0, oa1, oa2, oa3, b0, b1);
            mma_tf32(f1[nb], ob0, ob1, ob2, ob3, b0, b1);
        }
    }

    // write final output: out[b, q0+m, h*64+col] with row stride CE
    float* outp = out + (size_t)b * CT * CE + h * 64 + (size_t)q0 * CE;
#pragma unroll
    for (int nb = 0; nb < 8; nb++) {
        *(float2*)(outp + (size_t)(m0 + g)      * CE + nb * 8 + 2 * c) = make_float2(f0[nb][0], f0[nb][1]);
        *(float2*)(outp + (size_t)(m0 + g + 8)  * CE + nb * 8 + 2 * c) = make_float2(f0[nb][2], f0[nb][3]);
        *(float2*)(outp + (size_t)(m0 + g + 16) * CE + nb * 8 + 2 * c) = make_float2(f1[nb][0], f1[nb][1]);
        *(float2*)(outp + (size_t)(m0 + g + 24) * CE + nb * 8 + 2 * c) = make_float2(f1[nb][2], f1[nb][3]);
    }
}

// ---------------------------------------------------------------------------
extern "C" void kernel_launch(void* const* d_in, const int* in_sizes, int n_in,
                              void* d_out, int out_size)
{
    (void)in_sizes; (void)n_in; (void)out_size;
    const float* source = (const float*)d_in[0];
    const float* target = (const float*)d_in[1];
    const float* W_q    = (const float*)d_in[2];
    const float* W_v    = (const float*)d_in[3];
    const float* W_o    = (const float*)d_in[4];
    const float* W_ih   = (const float*)d_in[5];
    const float* W_hh   = (const float*)d_in[6];
    const float* b_ih   = (const float*)d_in[7];
    const float* b_hh   = (const float*)d_in[8];
    float* out = (float*)d_out;

    void *pV, *pNW;
    cudaGetSymbolAddress(&pV,  g_V);
    cudaGetSymbolAddress(&pNW, g_NW);
    float* Vb  = (float*)pV;
    float* NWb = (float*)pNW;

    const int pre_smem = (128 * 68 + 64 * 68) * (int)sizeof(float);    // 52224
    cudaFuncSetAttribute(fused_pre_kernel,
                         cudaFuncAttributeMaxDynamicSharedMemorySize, pre_smem);
    const int attn_smem = SM_ATTN_WORDS * (int)sizeof(unsigned);       // 103424
    cudaFuncSetAttribute(attn_fused_kernel,
                         cudaFuncAttributeMaxDynamicSharedMemorySize, attn_smem);

    // RNN (128 blocks, dispatched first) + V projection (1024 blocks), concurrent
    fused_pre_kernel<<<128 + 1024, 128, pre_smem>>>(
        target, W_v, W_ih, W_hh, b_ih, b_hh, NWb, Vb);

    // Q-proj + flash attention + O-proj, writes d_out directly
    attn_fused_kernel<<<dim3(CT / 128, CB * CH), 128, attn_smem>>>(
        source, W_q, NWb, Vb, W_o, out);
}

// round 17
// speedup vs baseline: 1.0506x; 1.0506x over previous
#include <cuda_runtime.h>
#include <math.h>

#define CB 8
#define CT 1024
#define CE 1024
#define CH 16
#define CD 64

// Scratch (device globals). Layout [b*H+h][t][64] contiguous.
__device__ float g_V  [CB*CH*CT*CD];
__device__ float g_NW [CB*CH*CT*CD];

// ---------------------------------------------------------------------------
// helpers
// ---------------------------------------------------------------------------
__device__ __forceinline__ unsigned f2tf32(float x) {
    unsigned r;
    asm("cvt.rna.tf32.f32 %0, %1;" : "=r"(r) : "f"(x));
    return r;
}
__device__ __forceinline__ float rnd_tf32(float x) {
    return __uint_as_float(f2tf32(x));
}
__device__ __forceinline__ float ex2_fast(float x) {
    float y;
    asm("ex2.approx.f32 %0, %1;" : "=f"(y) : "f"(x));
    return y;
}
__device__ __forceinline__ float tanh_fast(float x) {
    float y;
    asm("tanh.approx.f32 %0, %1;" : "=f"(y) : "f"(x));
    return y;
}
__device__ __forceinline__ void mma_tf32(float* d,
    unsigned a0, unsigned a1, unsigned a2, unsigned a3,
    unsigned b0, unsigned b1)
{
    asm volatile(
        "mma.sync.aligned.m16n8k8.row.col.f32.tf32.tf32.f32 "
        "{%0,%1,%2,%3}, {%4,%5,%6,%7}, {%8,%9}, {%0,%1,%2,%3};"
        : "+f"(d[0]), "+f"(d[1]), "+f"(d[2]), "+f"(d[3])
        : "r"(a0), "r"(a1), "r"(a2), "r"(a3), "r"(b0), "r"(b1));
}
__device__ __forceinline__ void cp_async16(unsigned saddr, const void* gptr) {
    asm volatile("cp.async.cg.shared.global [%0], [%1], 16;"
                 :: "r"(saddr), "l"(gptr));
}
#define CP_COMMIT() asm volatile("cp.async.commit_group;")
#define CP_WAIT0()  asm volatile("cp.async.wait_group 0;")

// ---------------------------------------------------------------------------
// V projection on tensor cores (dedicated launch): Y[128,64] tile =
// X[128,64] @ W[64,64] per (b,h); output rounded to tf32 so attention
// can consume raw bits.
// ---------------------------------------------------------------------------
__global__ __launch_bounds__(128) void proj_v_kernel(
    const float* __restrict__ target, const float* __restrict__ W_v,
    float* __restrict__ Vout)
{
    extern __shared__ unsigned psm[];
    float*    Xs = (float*)psm;            // 128 x 68 raw floats
    unsigned* Ws = psm + 128 * 68;         // 64 x 68 tf32 bits

    const int bh = blockIdx.y;
    const int b = bh >> 4, h = bh & 15;
    const int t0 = blockIdx.x << 7;
    const float* Xp = target + (size_t)b * CT * CE + h * 64 + (size_t)t0 * CE;
    float* Yp = Vout + (size_t)bh * CT * 64 + (size_t)t0 * 64;
    const float* Wp = W_v + h * 4096;
    const int tid = threadIdx.x;
    const int wid = tid >> 5, lane = tid & 31;
    const int g = lane >> 2, c = lane & 3;
    const int m0 = wid * 32;

#pragma unroll
    for (int k = 0; k < 16; k++) {
        int i = tid + k * 128;
        int r = i >> 4, c4 = i & 15;
        float4 v = *(const float4*)(Xp + (size_t)r * CE + c4 * 4);
        *(float4*)&Xs[r * 68 + c4 * 4] = v;
    }
#pragma unroll
    for (int k = 0; k < 8; k++) {
        int i = tid + k * 128;
        int d = i >> 4, c4 = i & 15;
        float4 v = *(const float4*)(Wp + d * 64 + c4 * 4);
        uint4 u = make_uint4(f2tf32(v.x), f2tf32(v.y), f2tf32(v.z), f2tf32(v.w));
        *(uint4*)&Ws[d * 68 + c4 * 4] = u;
    }
    __syncthreads();

    float acc0[8][4], acc1[8][4];
#pragma unroll
    for (int nb = 0; nb < 8; nb++)
#pragma unroll
        for (int k = 0; k < 4; k++) { acc0[nb][k] = 0.f; acc1[nb][k] = 0.f; }

#pragma unroll
    for (int kc = 0; kc < 8; kc++) {
        unsigned a0 = f2tf32(Xs[(m0 + g)      * 68 + kc * 8 + c]);
        unsigned a1 = f2tf32(Xs[(m0 + g + 8)  * 68 + kc * 8 + c]);
        unsigned a2 = f2tf32(Xs[(m0 + g)      * 68 + kc * 8 + c + 4]);
        unsigned a3 = f2tf32(Xs[(m0 + g + 8)  * 68 + kc * 8 + c + 4]);
        unsigned e0 = f2tf32(Xs[(m0 + g + 16) * 68 + kc * 8 + c]);
        unsigned e1 = f2tf32(Xs[(m0 + g + 24) * 68 + kc * 8 + c]);
        unsigned e2 = f2tf32(Xs[(m0 + g + 16) * 68 + kc * 8 + c + 4]);
        unsigned e3 = f2tf32(Xs[(m0 + g + 24) * 68 + kc * 8 + c + 4]);
#pragma unroll
        for (int nb = 0; nb < 8; nb++) {
            unsigned b0 = Ws[(kc * 8 + c)     * 68 + nb * 8 + g];
            unsigned b1 = Ws[(kc * 8 + c + 4) * 68 + nb * 8 + g];
            mma_tf32(acc0[nb], a0, a1, a2, a3, b0, b1);
            mma_tf32(acc1[nb], e0, e1, e2, e3, b0, b1);
        }
    }
#pragma unroll
    for (int nb = 0; nb < 8; nb++) {
        *(float2*)(Yp + (size_t)(m0 + g)      * 64 + nb * 8 + 2 * c) = make_float2(rnd_tf32(acc0[nb][0]), rnd_tf32(acc0[nb][1]));
        *(float2*)(Yp + (size_t)(m0 + g + 8)  * 64 + nb * 8 + 2 * c) = make_float2(rnd_tf32(acc0[nb][2]), rnd_tf32(acc0[nb][3]));
        *(float2*)(Yp + (size_t)(m0 + g + 16) * 64 + nb * 8 + 2 * c) = make_float2(rnd_tf32(acc1[nb][0]), rnd_tf32(acc1[nb][1]));
        *(float2*)(Yp + (size_t)(m0 + g + 24) * 64 + nb * 8 + 2 * c) = make_float2(rnd_tf32(acc1[nb][2]), rnd_tf32(acc1[nb][3]));
    }
}

// ---------------------------------------------------------------------------
// RNN (dedicated launch — chip to itself): one block per (b,h) chain.
// 128 threads, pair split-K, tanh.approx; keys stored rounded to tf32.
// ---------------------------------------------------------------------------
__global__ __launch_bounds__(128) void rnn_kernel(
    const float* __restrict__ target,
    const float* __restrict__ W_ih, const float* __restrict__ W_hh,
    const float* __restrict__ b_ih, const float* __restrict__ b_hh,
    float* __restrict__ NW)
{
    const int bh = blockIdx.x;
    const int b = bh >> 4, h = bh & 15;
    const int tid = threadIdx.x;
    const int e = tid >> 1, half = tid & 1;
    __shared__ float hs[2][64];

    float w[32];
    const float* wih = W_ih + h * 4096 + e * 64 + half * 32;
#pragma unroll
    for (int j = 0; j < 32; j++) w[j] = wih[j];
    const float bsum = b_ih[h * 64 + e] + b_hh[h * 64 + e];

    if (half == 0)
        hs[0][e] = target[(size_t)b * CT * CE + h * 64 + e];
    __syncthreads();

    // step 1: W_ih only
    {
        float a0 = 0.f, a1 = 0.f, a2 = 0.f, a3 = 0.f;
        const float* hb = &hs[0][half * 32];
#pragma unroll
        for (int j = 0; j < 8; j++) {
            float4 hv = *(const float4*)&hb[j * 4];
            a0 += hv.x * w[j * 4 + 0];
            a1 += hv.y * w[j * 4 + 1];
            a2 += hv.z * w[j * 4 + 2];
            a3 += hv.w * w[j * 4 + 3];
        }
        float part = (a0 + a1) + (a2 + a3);
        part += __shfl_xor_sync(0xffffffffu, part, 1);
        float hcur = tanh_fast(part + bsum);
        if (half == 0) {
            NW[(size_t)bh * CT * 64 + e] = rnd_tf32(hcur);
            hs[1][e] = hcur;
        }
    }
    const float* whh = W_hh + h * 4096 + e * 64 + half * 32;
#pragma unroll
    for (int j = 0; j < 32; j++) w[j] += whh[j];   // W_sum for steps >= 2
    __syncthreads();

    float* nwp = NW + (size_t)bh * CT * 64 + e;
    int p = 1;
    for (int t = 1; t < CT; t++) {
        float a0 = 0.f, a1 = 0.f, a2 = 0.f, a3 = 0.f;
        const float* hb = &hs[p][half * 32];
#pragma unroll
        for (int j = 0; j < 8; j++) {
            float4 hv = *(const float4*)&hb[j * 4];
            a0 += hv.x * w[j * 4 + 0];
            a1 += hv.y * w[j * 4 + 1];
            a2 += hv.z * w[j * 4 + 2];
            a3 += hv.w * w[j * 4 + 3];
        }
        float part = (a0 + a1) + (a2 + a3);
        part += __shfl_xor_sync(0xffffffffu, part, 1);
        float hn = tanh_fast(part + bsum);
        if (half == 0) {
            nwp[(size_t)t * 64] = rnd_tf32(hn);
            hs[p ^ 1][e] = hn;
        }
        __syncthreads();
        p ^= 1;
    }
}

// ---------------------------------------------------------------------------
// Fused attention: Q-projection prologue + flash attention mainloop (tf32 mma,
// cp.async double-buffered K/V, max-free softmax, shfl P-transpose) +
// O-projection epilogue writing d_out directly. (unchanged from round 14)
// Smem: [K0][V0][K1][V1] (4 x 64x68) + [Wbuf 64x68] + [Qpk 4096].
// ---------------------------------------------------------------------------
#define AST 68
#define TILE_W (64 * AST)                      // 4352 words
#define SM_WBUF (4 * TILE_W)                   // 17408
#define SM_QPK (SM_WBUF + TILE_W)              // 21760
#define SM_ATTN_WORDS (SM_QPK + 4096)          // 25856 words = 103424 B

__global__ __launch_bounds__(128, 2) void attn_fused_kernel(
    const float* __restrict__ source, const float* __restrict__ W_q,
    const float* __restrict__ K, const float* __restrict__ V,
    const float* __restrict__ W_o, float* __restrict__ out)
{
    extern __shared__ unsigned sm[];
    unsigned* Wbuf = sm + SM_WBUF;
    unsigned* Qpk  = sm + SM_QPK;
    const unsigned sbase = (unsigned)__cvta_generic_to_shared(sm);

    const int bh = blockIdx.y;
    const int b = bh >> 4, h = bh & 15;
    const int q0 = blockIdx.x << 7;
    const int tid = threadIdx.x;
    const int wid = tid >> 5, lane = tid & 31;
    const int g = lane >> 2, c = lane & 3;
    const int m0 = wid * 32;

    const float* Kp = K + (size_t)bh * CT * 64;
    const float* Vp = V + (size_t)bh * CT * 64;

    // ---- kick off K/V tile 0 into buffer 0 ----
#pragma unroll
    for (int k = 0; k < 8; k++) {
        int i = tid + k * 128;
        int r = i >> 4, c4 = i & 15;
        unsigned off = (unsigned)(r * AST + c4 * 4) * 4u;
        cp_async16(sbase + off, Kp + r * 64 + c4 * 4);
        cp_async16(sbase + TILE_W * 4u + off, Vp + r * 64 + c4 * 4);
    }
    CP_COMMIT();

    // ---- Q-projection prologue (overlaps tile-0 DMA) ----
    {
        float* Qstage = (float*)(sm + 2 * TILE_W);   // 128 x 68
        const float* Xp = source + (size_t)b * CT * CE + h * 64 + (size_t)q0 * CE;
#pragma unroll
        for (int k = 0; k < 16; k++) {
            int i = tid + k * 128;
            int r = i >> 4, c4 = i & 15;
            float4 v = *(const float4*)(Xp + (size_t)r * CE + c4 * 4);
            *(float4*)&Qstage[r * AST + c4 * 4] = v;
        }
        const float qscale = 1.4426950408889634f / 256.0f;  // log2(e)/(8*32)
        const float* Wp = W_q + h * 4096;
#pragma unroll
        for (int k = 0; k < 8; k++) {
            int i = tid + k * 128;
            int d = i >> 4, c4 = i & 15;
            float4 v = *(const float4*)(Wp + d * 64 + c4 * 4);
            uint4 u = make_uint4(f2tf32(v.x * qscale), f2tf32(v.y * qscale),
                                 f2tf32(v.z * qscale), f2tf32(v.w * qscale));
            *(uint4*)&Wbuf[d * 68 + c4 * 4] = u;
        }
    }
    __syncthreads();

    // Q = X @ (Wq*qscale), C-frag accumulate
    float qc0[8][4], qc1[8][4];
#pragma unroll
    for (int nb = 0; nb < 8; nb++)
#pragma unroll
        for (int k = 0; k < 4; k++) { qc0[nb][k] = 0.f; qc1[nb][k] = 0.f; }
    {
        const float* Qstage = (const float*)(sm + 2 * TILE_W);
#pragma unroll
        for (int kc = 0; kc < 8; kc++) {
            unsigned a0 = f2tf32(Qstage[(m0 + g)      * AST + kc * 8 + c]);
            unsigned a1 = f2tf32(Qstage[(m0 + g + 8)  * AST + kc * 8 + c]);
            unsigned a2 = f2tf32(Qstage[(m0 + g)      * AST + kc * 8 + c + 4]);
            unsigned a3 = f2tf32(Qstage[(m0 + g + 8)  * AST + kc * 8 + c + 4]);
            unsigned e0 = f2tf32(Qstage[(m0 + g + 16) * AST + kc * 8 + c]);
            unsigned e1 = f2tf32(Qstage[(m0 + g + 24) * AST + kc * 8 + c]);
            unsigned e2 = f2tf32(Qstage[(m0 + g + 16) * AST + kc * 8 + c + 4]);
            unsigned e3 = f2tf32(Qstage[(m0 + g + 24) * AST + kc * 8 + c + 4]);
#pragma unroll
            for (int nb = 0; nb < 8; nb++) {
                unsigned b0 = Wbuf[(kc * 8 + c)     * 68 + nb * 8 + g];
                unsigned b1 = Wbuf[(kc * 8 + c + 4) * 68 + nb * 8 + g];
                mma_tf32(qc0[nb], a0, a1, a2, a3, b0, b1);
                mma_tf32(qc1[nb], e0, e1, e2, e3, b0, b1);
            }
        }
    }
    // transpose Q C-frags -> A-frags (half0 regs, half1 -> Qpk)
    unsigned qa[8][4];
#pragma unroll
    for (int kc = 0; kc < 8; kc++) {
        const int srcA = (lane & ~3) | (c >> 1);
        const int srcB = srcA + 2;
        float t0, t1;
        t0 = __shfl_sync(0xffffffffu, qc0[kc][0], srcA);
        t1 = __shfl_sync(0xffffffffu, qc0[kc][1], srcA);
        qa[kc][0] = f2tf32((c & 1) ? t1 : t0);
        t0 = __shfl_sync(0xffffffffu, qc0[kc][2], srcA);
        t1 = __shfl_sync(0xffffffffu, qc0[kc][3], srcA);
        qa[kc][1] = f2tf32((c & 1) ? t1 : t0);
        t0 = __shfl_sync(0xffffffffu, qc0[kc][0], srcB);
        t1 = __shfl_sync(0xffffffffu, qc0[kc][1], srcB);
        qa[kc][2] = f2tf32((c & 1) ? t1 : t0);
        t0 = __shfl_sync(0xffffffffu, qc0[kc][2], srcB);
        t1 = __shfl_sync(0xffffffffu, qc0[kc][3], srcB);
        qa[kc][3] = f2tf32((c & 1) ? t1 : t0);

        uint4 qb;
        t0 = __shfl_sync(0xffffffffu, qc1[kc][0], srcA);
        t1 = __shfl_sync(0xffffffffu, qc1[kc][1], srcA);
        qb.x = f2tf32((c & 1) ? t1 : t0);
        t0 = __shfl_sync(0xffffffffu, qc1[kc][2], srcA);
        t1 = __shfl_sync(0xffffffffu, qc1[kc][3], srcA);
        qb.y = f2tf32((c & 1) ? t1 : t0);
        t0 = __shfl_sync(0xffffffffu, qc1[kc][0], srcB);
        t1 = __shfl_sync(0xffffffffu, qc1[kc][1], srcB);
        qb.z = f2tf32((c & 1) ? t1 : t0);
        t0 = __shfl_sync(0xffffffffu, qc1[kc][2], srcB);
        t1 = __shfl_sync(0xffffffffu, qc1[kc][3], srcB);
        qb.w = f2tf32((c & 1) ? t1 : t0);
        *(uint4*)&Qpk[((wid * 8 + kc) * 32 + lane) * 4] = qb;
    }

    // ---- mainloop ----
    float oacc0[8][4], oacc1[8][4];
#pragma unroll
    for (int nb = 0; nb < 8; nb++)
#pragma unroll
        for (int k = 0; k < 4; k++) { oacc0[nb][k] = 0.f; oacc1[nb][k] = 0.f; }
    float lacc00 = 0.f, lacc01 = 0.f, lacc10 = 0.f, lacc11 = 0.f;

    for (int kt = 0; kt < 16; kt++) {
        CP_WAIT0();
        __syncthreads();

        if (kt < 15) {
            const float* Kt = Kp + (kt + 1) * 64 * 64;
            const float* Vt = Vp + (kt + 1) * 64 * 64;
            unsigned bofs = ((kt + 1) & 1) ? 2u * TILE_W * 4u : 0u;
#pragma unroll
            for (int k = 0; k < 8; k++) {
                int i = tid + k * 128;
                int r = i >> 4, c4 = i & 15;
                unsigned off = (unsigned)(r * AST + c4 * 4) * 4u;
                cp_async16(sbase + bofs + off, Kt + r * 64 + c4 * 4);
                cp_async16(sbase + bofs + TILE_W * 4u + off, Vt + r * 64 + c4 * 4);
            }
            CP_COMMIT();
        }

        const unsigned* Kr = sm + ((kt & 1) ? 2 * TILE_W : 0);
        const unsigned* Vr = Kr + TILE_W;

        // S = Q @ K^T (raw pre-rounded tf32 bits from smem)
        float s0[8][4], s1[8][4];
#pragma unroll
        for (int nb = 0; nb < 8; nb++)
#pragma unroll
            for (int k = 0; k < 4; k++) { s0[nb][k] = 0.f; s1[nb][k] = 0.f; }
#pragma unroll
        for (int kc = 0; kc < 8; kc++) {
            uint4 qb = *(const uint4*)&Qpk[((wid * 8 + kc) * 32 + lane) * 4];
#pragma unroll
            for (int nb = 0; nb < 8; nb++) {
                unsigned b0 = Kr[(nb * 8 + g) * AST + kc * 8 + c];
                unsigned b1 = Kr[(nb * 8 + g) * AST + kc * 8 + c + 4];
                mma_tf32(s0[nb], qa[kc][0], qa[kc][1], qa[kc][2], qa[kc][3], b0, b1);
                mma_tf32(s1[nb], qb.x, qb.y, qb.z, qb.w, b0, b1);
            }
        }

        // max-free softmax: P = 2^s
#pragma unroll
        for (int nb = 0; nb < 8; nb++) {
            s0[nb][0] = ex2_fast(s0[nb][0]); lacc00 += s0[nb][0];
            s0[nb][1] = ex2_fast(s0[nb][1]); lacc00 += s0[nb][1];
            s0[nb][2] = ex2_fast(s0[nb][2]); lacc01 += s0[nb][2];
            s0[nb][3] = ex2_fast(s0[nb][3]); lacc01 += s0[nb][3];
            s1[nb][0] = ex2_fast(s1[nb][0]); lacc10 += s1[nb][0];
            s1[nb][1] = ex2_fast(s1[nb][1]); lacc10 += s1[nb][1];
            s1[nb][2] = ex2_fast(s1[nb][2]); lacc11 += s1[nb][2];
            s1[nb][3] = ex2_fast(s1[nb][3]); lacc11 += s1[nb][3];
        }

        // O += P @ V (P transposed C-frag -> A-frag via shfl)
#pragma unroll
        for (int jc = 0; jc < 8; jc++) {
            const int srcA = (lane & ~3) | (c >> 1);
            const int srcB = srcA + 2;
            float t0, t1;
            unsigned pa0, pa1, pa2, pa3, pb0, pb1, pb2, pb3;
            t0 = __shfl_sync(0xffffffffu, s0[jc][0], srcA);
            t1 = __shfl_sync(0xffffffffu, s0[jc][1], srcA);
            pa0 = f2tf32((c & 1) ? t1 : t0);
            t0 = __shfl_sync(0xffffffffu, s0[jc][2], srcA);
            t1 = __shfl_sync(0xffffffffu, s0[jc][3], srcA);
            pa1 = f2tf32((c & 1) ? t1 : t0);
            t0 = __shfl_sync(0xffffffffu, s0[jc][0], srcB);
            t1 = __shfl_sync(0xffffffffu, s0[jc][1], srcB);
            pa2 = f2tf32((c & 1) ? t1 : t0);
            t0 = __shfl_sync(0xffffffffu, s0[jc][2], srcB);
            t1 = __shfl_sync(0xffffffffu, s0[jc][3], srcB);
            pa3 = f2tf32((c & 1) ? t1 : t0);

            t0 = __shfl_sync(0xffffffffu, s1[jc][0], srcA);
            t1 = __shfl_sync(0xffffffffu, s1[jc][1], srcA);
            pb0 = f2tf32((c & 1) ? t1 : t0);
            t0 = __shfl_sync(0xffffffffu, s1[jc][2], srcA);
            t1 = __shfl_sync(0xffffffffu, s1[jc][3], srcA);
            pb1 = f2tf32((c & 1) ? t1 : t0);
            t0 = __shfl_sync(0xffffffffu, s1[jc][0], srcB);
            t1 = __shfl_sync(0xffffffffu, s1[jc][1], srcB);
            pb2 = f2tf32((c & 1) ? t1 : t0);
            t0 = __shfl_sync(0xffffffffu, s1[jc][2], srcB);
            t1 = __shfl_sync(0xffffffffu, s1[jc][3], srcB);
            pb3 = f2tf32((c & 1) ? t1 : t0);

#pragma unroll
            for (int nb = 0; nb < 8; nb++) {
                unsigned vb0 = Vr[(jc * 8 + c)     * AST + nb * 8 + g];
                unsigned vb1 = Vr[(jc * 8 + c + 4) * AST + nb * 8 + g];
                mma_tf32(oacc0[nb], pa0, pa1, pa2, pa3, vb0, vb1);
                mma_tf32(oacc1[nb], pb0, pb1, pb2, pb3, vb0, vb1);
            }
        }
    }

    // ---- normalize ----
    float l00 = lacc00, l01 = lacc01, l10 = lacc10, l11 = lacc11;
#pragma unroll
    for (int off = 1; off <= 2; off <<= 1) {
        l00 += __shfl_xor_sync(0xffffffffu, l00, off);
        l01 += __shfl_xor_sync(0xffffffffu, l01, off);
        l10 += __shfl_xor_sync(0xffffffffu, l10, off);
        l11 += __shfl_xor_sync(0xffffffffu, l11, off);
    }
    float i00 = 1.f / l00, i01 = 1.f / l01, i10 = 1.f / l10, i11 = 1.f / l11;
#pragma unroll
    for (int nb = 0; nb < 8; nb++) {
        oacc0[nb][0] *= i00; oacc0[nb][1] *= i00;
        oacc0[nb][2] *= i01; oacc0[nb][3] *= i01;
        oacc1[nb][0] *= i10; oacc1[nb][1] *= i10;
        oacc1[nb][2] *= i11; oacc1[nb][3] *= i11;
    }

    // ---- O-projection epilogue: stage Wo into freed K0 buffer ----
    __syncthreads();     // all warps done with K/V buffers
    {
        const float* Wp = W_o + h * 4096;
#pragma unroll
        for (int k = 0; k < 8; k++) {
            int i = tid + k * 128;
            int d = i >> 4, c4 = i & 15;
            float4 v = *(const float4*)(Wp + d * 64 + c4 * 4);
            uint4 u = make_uint4(f2tf32(v.x), f2tf32(v.y), f2tf32(v.z), f2tf32(v.w));
            *(uint4*)&sm[d * 68 + c4 * 4] = u;
        }
    }
    __syncthreads();

    float f0[8][4], f1[8][4];
#pragma unroll
    for (int nb = 0; nb < 8; nb++)
#pragma unroll
        for (int k = 0; k < 4; k++) { f0[nb][k] = 0.f; f1[nb][k] = 0.f; }

#pragma unroll
    for (int kc = 0; kc < 8; kc++) {
        const int srcA = (lane & ~3) | (c >> 1);
        const int srcB = srcA + 2;
        float t0, t1;
        unsigned oa0, oa1, oa2, oa3, ob0, ob1, ob2, ob3;
        t0 = __shfl_sync(0xffffffffu, oacc0[kc][0], srcA);
        t1 = __shfl_sync(0xffffffffu, oacc0[kc][1], srcA);
        oa0 = f2tf32((c & 1) ? t1 : t0);
        t0 = __shfl_sync(0xffffffffu, oacc0[kc][2], srcA);
        t1 = __shfl_sync(0xffffffffu, oacc0[kc][3], srcA);
        oa1 = f2tf32((c & 1) ? t1 : t0);
        t0 = __shfl_sync(0xffffffffu, oacc0[kc][0], srcB);
        t1 = __shfl_sync(0xffffffffu, oacc0[kc][1], srcB);
        oa2 = f2tf32((c & 1) ? t1 : t0);
        t0 = __shfl_sync(0xffffffffu, oacc0[kc][2], srcB);
        t1 = __shfl_sync(0xffffffffu, oacc0[kc][3], srcB);
        oa3 = f2tf32((c & 1) ? t1 : t0);

        t0 = __shfl_sync(0xffffffffu, oacc1[kc][0], srcA);
        t1 = __shfl_sync(0xffffffffu, oacc1[kc][1], srcA);
        ob0 = f2tf32((c & 1) ? t1 : t0);
        t0 = __shfl_sync(0xffffffffu, oacc1[kc][2], srcA);
        t1 = __shfl_sync(0xffffffffu, oacc1[kc][3], srcA);
        ob1 = f2tf32((c & 1) ? t1 : t0);
        t0 = __shfl_sync(0xffffffffu, oacc1[kc][0], srcB);
        t1 = __shfl_sync(0xffffffffu, oacc1[kc][1], srcB);
        ob2 = f2tf32((c & 1) ? t1 : t0);
        t0 = __shfl_sync(0xffffffffu, oacc1[kc][2], srcB);
        t1 = __shfl_sync(0xffffffffu, oacc1[kc][3], srcB);
        ob3 = f2tf32((c & 1) ? t1 : t0);

#pragma unroll
        for (int nb = 0; nb < 8; nb++) {
            unsigned b0 = sm[(kc * 8 + c)     * 68 + nb * 8 + g];
            unsigned b1 = sm[(kc * 8 + c + 4) * 68 + nb * 8 + g];
            mma_tf32(f0[nb], oa0, oa1, oa2, oa3, b0, b1);
            mma_tf32(f1[nb], ob0, ob1, ob2, ob3, b0, b1);
        }
    }

    // write final output: out[b, q0+m, h*64+col] with row stride CE
    float* outp = out + (size_t)b * CT * CE + h * 64 + (size_t)q0 * CE;
#pragma unroll
    for (int nb = 0; nb < 8; nb++) {
        *(float2*)(outp + (size_t)(m0 + g)      * CE + nb * 8 + 2 * c) = make_float2(f0[nb][0], f0[nb][1]);
        *(float2*)(outp + (size_t)(m0 + g + 8)  * CE + nb * 8 + 2 * c) = make_float2(f0[nb][2], f0[nb][3]);
        *(float2*)(outp + (size_t)(m0 + g + 16) * CE + nb * 8 + 2 * c) = make_float2(f1[nb][0], f1[nb][1]);
        *(float2*)(outp + (size_t)(m0 + g + 24) * CE + nb * 8 + 2 * c) = make_float2(f1[nb][2], f1[nb][3]);
    }
}

// ---------------------------------------------------------------------------
extern "C" void kernel_launch(void* const* d_in, const int* in_sizes, int n_in,
                              void* d_out, int out_size)
{
    (void)in_sizes; (void)n_in; (void)out_size;
    const float* source = (const float*)d_in[0];
    const float* target = (const float*)d_in[1];
    const float* W_q    = (const float*)d_in[2];
    const float* W_v    = (const float*)d_in[3];
    const float* W_o    = (const float*)d_in[4];
    const float* W_ih   = (const float*)d_in[5];
    const float* W_hh   = (const float*)d_in[6];
    const float* b_ih   = (const float*)d_in[7];
    const float* b_hh   = (const float*)d_in[8];
    float* out = (float*)d_out;

    void *pV, *pNW;
    cudaGetSymbolAddress(&pV,  g_V);
    cudaGetSymbolAddress(&pNW, g_NW);
    float* Vb  = (float*)pV;
    float* NWb = (float*)pNW;

    const int proj_smem = (128 * 68 + 64 * 68) * (int)sizeof(float);   // 52224
    cudaFuncSetAttribute(proj_v_kernel,
                         cudaFuncAttributeMaxDynamicSharedMemorySize, proj_smem);
    const int attn_smem = SM_ATTN_WORDS * (int)sizeof(unsigned);       // 103424
    cudaFuncSetAttribute(attn_fused_kernel,
                         cudaFuncAttributeMaxDynamicSharedMemorySize, attn_smem);

    // V projection (dedicated, full chip)
    proj_v_kernel<<<dim3(CT / 128, CB * CH), 128, proj_smem>>>(target, W_v, Vb);

    // RNN (dedicated — chip to itself, no interference)
    rnn_kernel<<<CB * CH, 128>>>(target, W_ih, W_hh, b_ih, b_hh, NWb);

    // Q-proj + flash attention + O-proj, writes d_out directly
    attn_fused_kernel<<<dim3(CT / 128, CB * CH), 128, attn_smem>>>(
        source, W_q, NWb, Vb, W_o, out);
}